// round 1
// baseline (speedup 1.0000x reference)
#include <cuda_runtime.h>
#include <cuda_bf16.h>
#include <math.h>

#define KNN_K 16
#define C 128
#define D2 64
#define EPS 1e-5f
#define NMAX 100000
#define PB 256   // partial blocks for BN reduction

// ---------------- scratch (device globals; no allocation allowed) ----------------
__device__ float g_xp[NMAX * C];        // projected features
__device__ float g_xsmax[NMAX * C];     // pre-BN output
__device__ float g_M[3 * C];            // fused m1*m2*m3a_top
__device__ float g_cvec[C];             // fused bias vector
__device__ float g_part[PB * C];
__device__ float g_partsq[PB * C];
__device__ __align__(16) float g_scale[C];
__device__ __align__(16) float g_shift[C];

__device__ __forceinline__ float gelu_exact(float x) {
    return 0.5f * x * (1.0f + erff(x * 0.7071067811865476f));
}

// ---------------- kernel 0: fold the affine chain ----------------
// M[d][c]   = sum_b (m1@m2)[d][b] * m3a[b][c]          (b < 64, top rows of m3a)
// cvec[c]   = sum_b (m1_b@m2 + m2_b)[b] * m3a[b][c] + m3a_b[c]
__global__ void fold_kernel(const float* __restrict__ m1w, const float* __restrict__ m1b,
                            const float* __restrict__ m2w, const float* __restrict__ m2b,
                            const float* __restrict__ m3aw, const float* __restrict__ m3ab) {
    __shared__ float T[3 * D2];
    __shared__ float U[D2];
    int tid = threadIdx.x;
    for (int idx = tid; idx < 3 * D2; idx += blockDim.x) {
        int d = idx / D2, b = idx % D2;
        float s = 0.f;
        for (int a = 0; a < D2; a++) s = fmaf(m1w[d * D2 + a], m2w[a * D2 + b], s);
        T[idx] = s;
    }
    if (tid < D2) {
        int b = tid;
        float s = m2b[b];
        for (int a = 0; a < D2; a++) s = fmaf(m1b[a], m2w[a * D2 + b], s);
        U[b] = s;
    }
    __syncthreads();
    if (tid < C) {
        int c = tid;
        for (int d = 0; d < 3; d++) {
            float s = 0.f;
            for (int b = 0; b < D2; b++) s = fmaf(T[d * D2 + b], m3aw[b * C + c], s);
            g_M[d * C + c] = s;
        }
        float s = m3ab[c];
        for (int b = 0; b < D2; b++) s = fmaf(U[b], m3aw[b * C + c], s);
        g_cvec[c] = s;
    }
}

// ---------------- kernel 1: xp = x @ W ----------------
__global__ __launch_bounds__(256) void proj_kernel(const float* __restrict__ x,
                                                   const float* __restrict__ W, int N) {
    __shared__ float sXt[C * 36];  // transposed x tile, padded stride 36
    int tid = threadIdx.x;
    int r0 = blockIdx.x * 32;
    for (int idx = tid; idx < 32 * C; idx += 256) {
        int row = idx >> 7, cc = idx & 127;
        int gr = r0 + row; if (gr >= N) gr = N - 1;
        sXt[cc * 36 + row] = x[(size_t)gr * C + cc];
    }
    __syncthreads();
    int c = tid & 127;
    int g = tid >> 7;  // row half: 0 or 1
    float acc[16];
#pragma unroll
    for (int u = 0; u < 16; u++) acc[u] = 0.f;
#pragma unroll 8
    for (int r = 0; r < C; r++) {
        float w = __ldg(W + r * C + c);
        const float4* xb = (const float4*)(sXt + r * 36 + g * 16);
        float4 a0 = xb[0], a1 = xb[1], a2 = xb[2], a3 = xb[3];
        acc[0]  = fmaf(a0.x, w, acc[0]);  acc[1]  = fmaf(a0.y, w, acc[1]);
        acc[2]  = fmaf(a0.z, w, acc[2]);  acc[3]  = fmaf(a0.w, w, acc[3]);
        acc[4]  = fmaf(a1.x, w, acc[4]);  acc[5]  = fmaf(a1.y, w, acc[5]);
        acc[6]  = fmaf(a1.z, w, acc[6]);  acc[7]  = fmaf(a1.w, w, acc[7]);
        acc[8]  = fmaf(a2.x, w, acc[8]);  acc[9]  = fmaf(a2.y, w, acc[9]);
        acc[10] = fmaf(a2.z, w, acc[10]); acc[11] = fmaf(a2.w, w, acc[11]);
        acc[12] = fmaf(a3.x, w, acc[12]); acc[13] = fmaf(a3.y, w, acc[13]);
        acc[14] = fmaf(a3.z, w, acc[14]); acc[15] = fmaf(a3.w, w, acc[15]);
    }
#pragma unroll
    for (int u = 0; u < 16; u++) {
        int rr = r0 + g * 16 + u;
        if (rr < N) g_xp[(size_t)rr * C + c] = acc[u];
    }
}

// ---------------- kernel 2: fused per-point edge MLP + max aggregate ----------------
// smem float offsets
#define OFF_W3B 0          // 16384  m3b weights
#define OFF_A3  16384      // 8192   m3a bottom rows (64..127)
#define OFF_H   24576      // 2*2112 h, row stride 132
#define OFF_M   28800      // 384
#define OFF_CV  29184      // 128
#define OFF_M1  29312      // 192
#define OFF_M1B 29504      // 64
#define OFF_B3B 29568      // 128
#define OFF_XPI 29696      // 256
#define OFF_PL  29952      // 128
#define OFF_RED 30080      // 1024
#define OFF_DX  31104      // 32
#define OFF_DY  31136      // 32
#define OFF_DZ  31168      // 32
#define OFF_JN  31200      // 32 ints
#define SMEM_FLOATS 31232
#define SMEM_BYTES (SMEM_FLOATS * 4)

__global__ __launch_bounds__(256, 1) void main_kernel(
    const float* __restrict__ xyz, const int* __restrict__ knn,
    const float* __restrict__ m1w, const float* __restrict__ m1b,
    const float* __restrict__ m3aw, const float* __restrict__ m3bw,
    const float* __restrict__ m3bb, int N) {
    extern __shared__ float smem[];
    float* sW3b = smem + OFF_W3B;
    float* sA3  = smem + OFF_A3;
    float* sh   = smem + OFF_H;
    float* sM   = smem + OFF_M;
    float* scv  = smem + OFF_CV;
    float* sm1  = smem + OFF_M1;
    float* sm1b = smem + OFF_M1B;
    float* sb3b = smem + OFF_B3B;
    float* sxpi = smem + OFF_XPI;
    float* spl  = smem + OFF_PL;
    float* sred = smem + OFF_RED;
    float* sdx  = smem + OFF_DX;
    float* sdy  = smem + OFF_DY;
    float* sdz  = smem + OFF_DZ;
    int*   sjn  = (int*)(smem + OFF_JN);

    const int tid = threadIdx.x;
    const int sub = tid >> 7;       // which of the 2 points in this block
    const int wg_tid = tid & 127;

    // stage weights once per block (persistent blocks)
    for (int idx = tid; idx < C * C; idx += 256) sW3b[idx] = __ldg(m3bw + idx);
    for (int idx = tid; idx < D2 * C; idx += 256) sA3[idx] = __ldg(m3aw + D2 * C + idx);
    for (int idx = tid; idx < 3 * C; idx += 256) sM[idx] = g_M[idx];
    for (int idx = tid; idx < C; idx += 256) { scv[idx] = g_cvec[idx]; sb3b[idx] = m3bb[idx]; }
    for (int idx = tid; idx < 3 * D2; idx += 256) sm1[idx] = m1w[idx];
    for (int idx = tid; idx < D2; idx += 256) sm1b[idx] = m1b[idx];
    __syncthreads();

    const int npairs = (N + 1) >> 1;
    for (int pair = blockIdx.x; pair < npairs; pair += gridDim.x) {
        const int i = pair * 2 + sub;
        const bool valid = (i < N);

        // phase a: neighbor indices, xyz deltas, center xp row
        if (valid) {
            if (wg_tid < KNN_K) {
                int k = wg_tid;
                int j = knn[(size_t)i * KNN_K + k];
                sjn[sub * KNN_K + k] = j;
                float cx = xyz[(size_t)i * 3 + 0], cy = xyz[(size_t)i * 3 + 1], cz = xyz[(size_t)i * 3 + 2];
                sdx[sub * KNN_K + k] = xyz[(size_t)j * 3 + 0] - cx;
                sdy[sub * KNN_K + k] = xyz[(size_t)j * 3 + 1] - cy;
                sdz[sub * KNN_K + k] = xyz[(size_t)j * 3 + 2] - cz;
            }
            sxpi[sub * C + wg_tid] = g_xp[(size_t)i * C + wg_tid];
        }
        __syncthreads();

        // phase b: p0 + p_local (max over k)
        if (valid && wg_tid < D2) {
            int cc = wg_tid;
            float w0 = sm1[cc], w1 = sm1[D2 + cc], w2 = sm1[2 * D2 + cc], b = sm1b[cc];
            float pl = -3.4e38f;
#pragma unroll
            for (int k = 0; k < KNN_K; k++) {
                float v = fmaf(sdx[sub * KNN_K + k], w0,
                          fmaf(sdy[sub * KNN_K + k], w1,
                          fmaf(sdz[sub * KNN_K + k], w2, b)));
                pl = fmaxf(pl, v);
            }
            spl[sub * D2 + cc] = pl;
        }
        __syncthreads();

        // phase c: base + per-edge pre-activation + GELU -> sh
        if (valid) {
            int c = wg_tid;
            float base = scv[c];
#pragma unroll 16
            for (int r = 0; r < D2; r++) base = fmaf(spl[sub * D2 + r], sA3[r * C + c], base);
            float M0 = sM[c], M1 = sM[C + c], M2 = sM[2 * C + c];
#pragma unroll
            for (int k = 0; k < KNN_K; k++) {
                float hp = fmaf(sdx[sub * KNN_K + k], M0,
                           fmaf(sdy[sub * KNN_K + k], M1,
                           fmaf(sdz[sub * KNN_K + k], M2, base)));
                sh[sub * 2112 + k * 132 + c] = gelu_exact(hp);
            }
        }
        __syncthreads();

        // phase d: pe = h @ m3b, add gather diff, max over k (warp part)
        if (valid) {
            const int kk = wg_tid >> 3;
            const int t  = wg_tid & 7;
            const float* hrow = sh + sub * 2112 + kk * 132;
            const int j = sjn[sub * KNN_K + kk];
            const float* xnb = g_xp + (size_t)j * C + t * 4;
            float4 gn0 = *(const float4*)(xnb);
            float4 gn1 = *(const float4*)(xnb + 32);
            float4 gn2 = *(const float4*)(xnb + 64);
            float4 gn3 = *(const float4*)(xnb + 96);

            unsigned long long acc[8];
#pragma unroll
            for (int q = 0; q < 8; q++) acc[q] = 0ull;

#pragma unroll 4
            for (int r = 0; r < C; r++) {
                float hv = hrow[r];
                unsigned long long h2;
                asm("mov.b64 %0, {%1, %1};" : "=l"(h2) : "f"(hv));
                const float* wr = sW3b + r * C + t * 4;
#pragma unroll
                for (int q = 0; q < 4; q++) {
                    ulonglong2 w2 = *(const ulonglong2*)(wr + 32 * q);
                    asm("fma.rn.f32x2 %0, %1, %2, %0;" : "+l"(acc[2 * q])     : "l"(h2), "l"(w2.x));
                    asm("fma.rn.f32x2 %0, %1, %2, %0;" : "+l"(acc[2 * q + 1]) : "l"(h2), "l"(w2.y));
                }
            }

            float m[16];
            float4 gn[4] = {gn0, gn1, gn2, gn3};
#pragma unroll
            for (int q = 0; q < 4; q++) {
#pragma unroll
                for (int p = 0; p < 2; p++) {
                    float v0, v1;
                    asm("mov.b64 {%0, %1}, %2;" : "=f"(v0), "=f"(v1) : "l"(acc[2 * q + p]));
                    int c0 = t * 4 + 32 * q + 2 * p;
                    const float* gf = (const float*)&gn[q];
                    m[q * 4 + 2 * p]     = v0 + sb3b[c0]     + gf[2 * p]     - sxpi[sub * C + c0];
                    m[q * 4 + 2 * p + 1] = v1 + sb3b[c0 + 1] + gf[2 * p + 1] - sxpi[sub * C + c0 + 1];
                }
            }
            // reduce over the 4 k's within this warp (lanes differ in bits 3,4)
#pragma unroll
            for (int idx = 0; idx < 16; idx++)
                m[idx] = fmaxf(m[idx], __shfl_xor_sync(0xffffffffu, m[idx], 8));
#pragma unroll
            for (int idx = 0; idx < 16; idx++)
                m[idx] = fmaxf(m[idx], __shfl_xor_sync(0xffffffffu, m[idx], 16));
            if ((wg_tid & 31) < 8) {
                int w = wg_tid >> 5;
#pragma unroll
                for (int idx = 0; idx < 16; idx++) {
                    int c = t * 4 + 32 * (idx >> 2) + (idx & 3);
                    sred[sub * 512 + w * C + c] = m[idx];
                }
            }
        }
        __syncthreads();

        // phase e: reduce across the 4 warps, store
        if (valid) {
            int c = wg_tid;
            float v = fmaxf(fmaxf(sred[sub * 512 + c], sred[sub * 512 + C + c]),
                            fmaxf(sred[sub * 512 + 2 * C + c], sred[sub * 512 + 3 * C + c]));
            g_xsmax[(size_t)i * C + c] = v;
        }
        __syncthreads();
    }
}

// ---------------- kernel 3: BatchNorm ----------------
__global__ void bn_partial_kernel(int N) {
    int c = threadIdx.x;
    int rpb = (N + PB - 1) / PB;
    int r0 = blockIdx.x * rpb;
    int r1 = min(N, r0 + rpb);
    float s = 0.f, q = 0.f;
    for (int r = r0; r < r1; r++) {
        float v = g_xsmax[(size_t)r * C + c];
        s += v;
        q = fmaf(v, v, q);
    }
    g_part[blockIdx.x * C + c] = s;
    g_partsq[blockIdx.x * C + c] = q;
}

__global__ void bn_final_kernel(const float* __restrict__ gamma, const float* __restrict__ beta, int N) {
    int c = threadIdx.x;
    float s = 0.f, q = 0.f;
    for (int b = 0; b < PB; b++) { s += g_part[b * C + c]; q += g_partsq[b * C + c]; }
    float mean = s / (float)N;
    float var = q / (float)N - mean * mean;
    if (var < 0.f) var = 0.f;
    float sc = rsqrtf(var + EPS) * gamma[c];
    g_scale[c] = sc;
    g_shift[c] = beta[c] - mean * sc;
}

__global__ void bn_apply_kernel(float* __restrict__ out, int N) {
    int idx = blockIdx.x * blockDim.x + threadIdx.x;
    int total4 = N * (C / 4);
    if (idx >= total4) return;
    float4 v = ((const float4*)g_xsmax)[idx];
    int c4 = idx & 31;
    float4 sc = ((const float4*)g_scale)[c4];
    float4 sf = ((const float4*)g_shift)[c4];
    float4 o;
    o.x = fmaf(v.x, sc.x, sf.x);
    o.y = fmaf(v.y, sc.y, sf.y);
    o.z = fmaf(v.z, sc.z, sf.z);
    o.w = fmaf(v.w, sc.w, sf.w);
    ((float4*)out)[idx] = o;
}

// ---------------- launch ----------------
extern "C" void kernel_launch(void* const* d_in, const int* in_sizes, int n_in,
                              void* d_out, int out_size) {
    const float* xyz  = (const float*)d_in[0];
    const float* x    = (const float*)d_in[1];
    const int*   knn  = (const int*)d_in[2];
    const float* W    = (const float*)d_in[3];
    const float* m1w  = (const float*)d_in[4];
    const float* m1b  = (const float*)d_in[5];
    const float* m2w  = (const float*)d_in[6];
    const float* m2b  = (const float*)d_in[7];
    const float* m3aw = (const float*)d_in[8];
    const float* m3ab = (const float*)d_in[9];
    const float* m3bw = (const float*)d_in[10];
    const float* m3bb = (const float*)d_in[11];
    const float* gamma = (const float*)d_in[12];
    const float* beta  = (const float*)d_in[13];

    int N = in_sizes[0] / 3;

    static int sms = 0;
    if (sms == 0) {
        cudaDeviceGetAttribute(&sms, cudaDevAttrMultiProcessorCount, 0);
        cudaFuncSetAttribute(main_kernel, cudaFuncAttributeMaxDynamicSharedMemorySize, SMEM_BYTES);
    }

    fold_kernel<<<1, 128>>>(m1w, m1b, m2w, m2b, m3aw, m3ab);
    proj_kernel<<<(N + 31) / 32, 256>>>(x, W, N);
    main_kernel<<<sms, 256, SMEM_BYTES>>>(xyz, knn, m1w, m1b, m3aw, m3bw, m3bb, N);
    bn_partial_kernel<<<PB, C>>>(N);
    bn_final_kernel<<<1, C>>>(gamma, beta, N);
    int total4 = N * (C / 4);
    bn_apply_kernel<<<(total4 + 255) / 256, 256>>>((float*)d_out, N);
}

// round 4
// speedup vs baseline: 1.0024x; 1.0024x over previous
#include <cuda_runtime.h>
#include <cuda_bf16.h>
#include <math.h>

#define KNN_K 16
#define C 128
#define D2 64
#define EPS 1e-5f
#define NMAX 100000
#define PB 256   // partial blocks for BN reduction

// ---------------- scratch (device globals; no allocation allowed) ----------------
__device__ float g_xp[NMAX * C];        // projected features
__device__ float g_xsmax[NMAX * C];     // pre-BN output
__device__ float g_M[3 * C];            // fused m1*m2*m3a_top
__device__ float g_cvec[C];             // fused bias vector
__device__ float g_part[PB * C];
__device__ float g_partsq[PB * C];
__device__ __align__(16) float g_scale[C];
__device__ __align__(16) float g_shift[C];

__device__ __forceinline__ float gelu_exact(float x) {
    return 0.5f * x * (1.0f + erff(x * 0.7071067811865476f));
}

// ---------------- kernel 0: fold the affine chain ----------------
// M[d][c]   = sum_b (m1@m2)[d][b] * m3a[b][c]          (b < 64, top rows of m3a)
// cvec[c]   = sum_b (m1_b@m2 + m2_b)[b] * m3a[b][c] + m3a_b[c]
__global__ void fold_kernel(const float* __restrict__ m1w, const float* __restrict__ m1b,
                            const float* __restrict__ m2w, const float* __restrict__ m2b,
                            const float* __restrict__ m3aw, const float* __restrict__ m3ab) {
    __shared__ float T[3 * D2];
    __shared__ float U[D2];
    int tid = threadIdx.x;
    for (int idx = tid; idx < 3 * D2; idx += blockDim.x) {
        int d = idx / D2, b = idx % D2;
        float s = 0.f;
        for (int a = 0; a < D2; a++) s = fmaf(m1w[d * D2 + a], m2w[a * D2 + b], s);
        T[idx] = s;
    }
    if (tid < D2) {
        int b = tid;
        float s = m2b[b];
        for (int a = 0; a < D2; a++) s = fmaf(m1b[a], m2w[a * D2 + b], s);
        U[b] = s;
    }
    __syncthreads();
    if (tid < C) {
        int c = tid;
        for (int d = 0; d < 3; d++) {
            float s = 0.f;
            for (int b = 0; b < D2; b++) s = fmaf(T[d * D2 + b], m3aw[b * C + c], s);
            g_M[d * C + c] = s;
        }
        float s = m3ab[c];
        for (int b = 0; b < D2; b++) s = fmaf(U[b], m3aw[b * C + c], s);
        g_cvec[c] = s;
    }
}

// ---------------- kernel 1: xp = x @ W ----------------
__global__ __launch_bounds__(256) void proj_kernel(const float* __restrict__ x,
                                                   const float* __restrict__ W, int N) {
    __shared__ float sXt[C * 36];  // transposed x tile, padded stride 36
    int tid = threadIdx.x;
    int r0 = blockIdx.x * 32;
    for (int idx = tid; idx < 32 * C; idx += 256) {
        int row = idx >> 7, cc = idx & 127;
        int gr = r0 + row; if (gr >= N) gr = N - 1;
        sXt[cc * 36 + row] = x[(size_t)gr * C + cc];
    }
    __syncthreads();
    int c = tid & 127;
    int g = tid >> 7;  // row half: 0 or 1
    float acc[16];
#pragma unroll
    for (int u = 0; u < 16; u++) acc[u] = 0.f;
#pragma unroll 8
    for (int r = 0; r < C; r++) {
        float w = __ldg(W + r * C + c);
        const float4* xb = (const float4*)(sXt + r * 36 + g * 16);
        float4 a0 = xb[0], a1 = xb[1], a2 = xb[2], a3 = xb[3];
        acc[0]  = fmaf(a0.x, w, acc[0]);  acc[1]  = fmaf(a0.y, w, acc[1]);
        acc[2]  = fmaf(a0.z, w, acc[2]);  acc[3]  = fmaf(a0.w, w, acc[3]);
        acc[4]  = fmaf(a1.x, w, acc[4]);  acc[5]  = fmaf(a1.y, w, acc[5]);
        acc[6]  = fmaf(a1.z, w, acc[6]);  acc[7]  = fmaf(a1.w, w, acc[7]);
        acc[8]  = fmaf(a2.x, w, acc[8]);  acc[9]  = fmaf(a2.y, w, acc[9]);
        acc[10] = fmaf(a2.z, w, acc[10]); acc[11] = fmaf(a2.w, w, acc[11]);
        acc[12] = fmaf(a3.x, w, acc[12]); acc[13] = fmaf(a3.y, w, acc[13]);
        acc[14] = fmaf(a3.z, w, acc[14]); acc[15] = fmaf(a3.w, w, acc[15]);
    }
#pragma unroll
    for (int u = 0; u < 16; u++) {
        int rr = r0 + g * 16 + u;
        if (rr < N) g_xp[(size_t)rr * C + c] = acc[u];
    }
}

// ---------------- kernel 2: fused per-point edge MLP + max aggregate ----------------
// smem float offsets
#define OFF_W3B 0          // 16384  m3b weights
#define OFF_A3  16384      // 8192   m3a bottom rows (64..127)
#define OFF_H   24576      // 2*2112 h, row stride 132
#define OFF_M   28800      // 384
#define OFF_CV  29184      // 128
#define OFF_M1  29312      // 192
#define OFF_M1B 29504      // 64
#define OFF_B3B 29568      // 128
#define OFF_XPI 29696      // 256
#define OFF_PL  29952      // 128
#define OFF_RED 30080      // 1024
#define OFF_DX  31104      // 32
#define OFF_DY  31136      // 32
#define OFF_DZ  31168      // 32
#define OFF_JN  31200      // 32 ints
#define SMEM_FLOATS 31232
#define SMEM_BYTES (SMEM_FLOATS * 4)

__global__ __launch_bounds__(256, 1) void main_kernel(
    const float* __restrict__ xyz, const int* __restrict__ knn,
    const float* __restrict__ m1w, const float* __restrict__ m1b,
    const float* __restrict__ m3aw, const float* __restrict__ m3bw,
    const float* __restrict__ m3bb, int N) {
    extern __shared__ float smem[];
    float* sW3b = smem + OFF_W3B;
    float* sA3  = smem + OFF_A3;
    float* sh   = smem + OFF_H;
    float* sM   = smem + OFF_M;
    float* scv  = smem + OFF_CV;
    float* sm1  = smem + OFF_M1;
    float* sm1b = smem + OFF_M1B;
    float* sb3b = smem + OFF_B3B;
    float* sxpi = smem + OFF_XPI;
    float* spl  = smem + OFF_PL;
    float* sred = smem + OFF_RED;
    float* sdx  = smem + OFF_DX;
    float* sdy  = smem + OFF_DY;
    float* sdz  = smem + OFF_DZ;
    int*   sjn  = (int*)(smem + OFF_JN);

    const int tid = threadIdx.x;
    const int sub = tid >> 7;       // which of the 2 points in this block
    const int wg_tid = tid & 127;

    // stage weights once per block (persistent blocks)
    for (int idx = tid; idx < C * C; idx += 256) sW3b[idx] = __ldg(m3bw + idx);
    for (int idx = tid; idx < D2 * C; idx += 256) sA3[idx] = __ldg(m3aw + D2 * C + idx);
    for (int idx = tid; idx < 3 * C; idx += 256) sM[idx] = g_M[idx];
    for (int idx = tid; idx < C; idx += 256) { scv[idx] = g_cvec[idx]; sb3b[idx] = m3bb[idx]; }
    for (int idx = tid; idx < 3 * D2; idx += 256) sm1[idx] = m1w[idx];
    for (int idx = tid; idx < D2; idx += 256) sm1b[idx] = m1b[idx];
    __syncthreads();

    const int npairs = (N + 1) >> 1;
    for (int pair = blockIdx.x; pair < npairs; pair += gridDim.x) {
        const int i = pair * 2 + sub;
        const bool valid = (i < N);

        // phase a: neighbor indices, xyz deltas, center xp row
        if (valid) {
            if (wg_tid < KNN_K) {
                int k = wg_tid;
                int j = knn[(size_t)i * KNN_K + k];
                sjn[sub * KNN_K + k] = j;
                float cx = xyz[(size_t)i * 3 + 0], cy = xyz[(size_t)i * 3 + 1], cz = xyz[(size_t)i * 3 + 2];
                sdx[sub * KNN_K + k] = xyz[(size_t)j * 3 + 0] - cx;
                sdy[sub * KNN_K + k] = xyz[(size_t)j * 3 + 1] - cy;
                sdz[sub * KNN_K + k] = xyz[(size_t)j * 3 + 2] - cz;
            }
            sxpi[sub * C + wg_tid] = g_xp[(size_t)i * C + wg_tid];
        }
        __syncthreads();

        // phase b: p0 + p_local (max over k)
        if (valid && wg_tid < D2) {
            int cc = wg_tid;
            float w0 = sm1[cc], w1 = sm1[D2 + cc], w2 = sm1[2 * D2 + cc], b = sm1b[cc];
            float pl = -3.4e38f;
#pragma unroll
            for (int k = 0; k < KNN_K; k++) {
                float v = fmaf(sdx[sub * KNN_K + k], w0,
                          fmaf(sdy[sub * KNN_K + k], w1,
                          fmaf(sdz[sub * KNN_K + k], w2, b)));
                pl = fmaxf(pl, v);
            }
            spl[sub * D2 + cc] = pl;
        }
        __syncthreads();

        // phase c: base + per-edge pre-activation + GELU -> sh
        if (valid) {
            int c = wg_tid;
            float base = scv[c];
#pragma unroll 16
            for (int r = 0; r < D2; r++) base = fmaf(spl[sub * D2 + r], sA3[r * C + c], base);
            float M0 = sM[c], M1 = sM[C + c], M2 = sM[2 * C + c];
#pragma unroll
            for (int k = 0; k < KNN_K; k++) {
                float hp = fmaf(sdx[sub * KNN_K + k], M0,
                           fmaf(sdy[sub * KNN_K + k], M1,
                           fmaf(sdz[sub * KNN_K + k], M2, base)));
                sh[sub * 2112 + k * 132 + c] = gelu_exact(hp);
            }
        }
        __syncthreads();

        // phase d: pe = h @ m3b, add gather diff, max over k (warp part)
        if (valid) {
            const int kk = wg_tid >> 3;
            const int t  = wg_tid & 7;
            const float* hrow = sh + sub * 2112 + kk * 132;
            const int j = sjn[sub * KNN_K + kk];
            const float* xnb = g_xp + (size_t)j * C + t * 4;
            float4 gn0 = *(const float4*)(xnb);
            float4 gn1 = *(const float4*)(xnb + 32);
            float4 gn2 = *(const float4*)(xnb + 64);
            float4 gn3 = *(const float4*)(xnb + 96);

            unsigned long long acc[8];
#pragma unroll
            for (int q = 0; q < 8; q++) acc[q] = 0ull;

#pragma unroll 4
            for (int r = 0; r < C; r++) {
                float hv = hrow[r];
                unsigned long long h2;
                asm("mov.b64 %0, {%1, %1};" : "=l"(h2) : "f"(hv));
                const float* wr = sW3b + r * C + t * 4;
#pragma unroll
                for (int q = 0; q < 4; q++) {
                    ulonglong2 w2 = *(const ulonglong2*)(wr + 32 * q);
                    asm("fma.rn.f32x2 %0, %1, %2, %0;" : "+l"(acc[2 * q])     : "l"(h2), "l"(w2.x));
                    asm("fma.rn.f32x2 %0, %1, %2, %0;" : "+l"(acc[2 * q + 1]) : "l"(h2), "l"(w2.y));
                }
            }

            float m[16];
            float4 gn[4] = {gn0, gn1, gn2, gn3};
#pragma unroll
            for (int q = 0; q < 4; q++) {
#pragma unroll
                for (int p = 0; p < 2; p++) {
                    float v0, v1;
                    asm("mov.b64 {%0, %1}, %2;" : "=f"(v0), "=f"(v1) : "l"(acc[2 * q + p]));
                    int c0 = t * 4 + 32 * q + 2 * p;
                    const float* gf = (const float*)&gn[q];
                    m[q * 4 + 2 * p]     = v0 + sb3b[c0]     + gf[2 * p]     - sxpi[sub * C + c0];
                    m[q * 4 + 2 * p + 1] = v1 + sb3b[c0 + 1] + gf[2 * p + 1] - sxpi[sub * C + c0 + 1];
                }
            }
            // reduce over the 4 k's within this warp (lanes differ in bits 3,4)
#pragma unroll
            for (int idx = 0; idx < 16; idx++)
                m[idx] = fmaxf(m[idx], __shfl_xor_sync(0xffffffffu, m[idx], 8));
#pragma unroll
            for (int idx = 0; idx < 16; idx++)
                m[idx] = fmaxf(m[idx], __shfl_xor_sync(0xffffffffu, m[idx], 16));
            if ((wg_tid & 31) < 8) {
                int w = wg_tid >> 5;
#pragma unroll
                for (int idx = 0; idx < 16; idx++) {
                    int c = t * 4 + 32 * (idx >> 2) + (idx & 3);
                    sred[sub * 512 + w * C + c] = m[idx];
                }
            }
        }
        __syncthreads();

        // phase e: reduce across the 4 warps, store
        if (valid) {
            int c = wg_tid;
            float v = fmaxf(fmaxf(sred[sub * 512 + c], sred[sub * 512 + C + c]),
                            fmaxf(sred[sub * 512 + 2 * C + c], sred[sub * 512 + 3 * C + c]));
            g_xsmax[(size_t)i * C + c] = v;
        }
        __syncthreads();
    }
}

// ---------------- kernel 3: BatchNorm ----------------
__global__ void bn_partial_kernel(int N) {
    int c = threadIdx.x;
    int rpb = (N + PB - 1) / PB;
    int r0 = blockIdx.x * rpb;
    int r1 = min(N, r0 + rpb);
    float s = 0.f, q = 0.f;
    for (int r = r0; r < r1; r++) {
        float v = g_xsmax[(size_t)r * C + c];
        s += v;
        q = fmaf(v, v, q);
    }
    g_part[blockIdx.x * C + c] = s;
    g_partsq[blockIdx.x * C + c] = q;
}

__global__ void bn_final_kernel(const float* __restrict__ gamma, const float* __restrict__ beta, int N) {
    int c = threadIdx.x;
    float s = 0.f, q = 0.f;
    for (int b = 0; b < PB; b++) { s += g_part[b * C + c]; q += g_partsq[b * C + c]; }
    float mean = s / (float)N;
    float var = q / (float)N - mean * mean;
    if (var < 0.f) var = 0.f;
    float sc = rsqrtf(var + EPS) * gamma[c];
    g_scale[c] = sc;
    g_shift[c] = beta[c] - mean * sc;
}

__global__ void bn_apply_kernel(float* __restrict__ out, int N) {
    int idx = blockIdx.x * blockDim.x + threadIdx.x;
    int total4 = N * (C / 4);
    if (idx >= total4) return;
    float4 v = ((const float4*)g_xsmax)[idx];
    int c4 = idx & 31;
    float4 sc = ((const float4*)g_scale)[c4];
    float4 sf = ((const float4*)g_shift)[c4];
    float4 o;
    o.x = fmaf(v.x, sc.x, sf.x);
    o.y = fmaf(v.y, sc.y, sf.y);
    o.z = fmaf(v.z, sc.z, sf.z);
    o.w = fmaf(v.w, sc.w, sf.w);
    ((float4*)out)[idx] = o;
}

// ---------------- launch ----------------
extern "C" void kernel_launch(void* const* d_in, const int* in_sizes, int n_in,
                              void* d_out, int out_size) {
    const float* xyz  = (const float*)d_in[0];
    const float* x    = (const float*)d_in[1];
    const int*   knn  = (const int*)d_in[2];
    const float* W    = (const float*)d_in[3];
    const float* m1w  = (const float*)d_in[4];
    const float* m1b  = (const float*)d_in[5];
    const float* m2w  = (const float*)d_in[6];
    const float* m2b  = (const float*)d_in[7];
    const float* m3aw = (const float*)d_in[8];
    const float* m3ab = (const float*)d_in[9];
    const float* m3bw = (const float*)d_in[10];
    const float* m3bb = (const float*)d_in[11];
    const float* gamma = (const float*)d_in[12];
    const float* beta  = (const float*)d_in[13];

    int N = in_sizes[0] / 3;

    static int sms = 0;
    if (sms == 0) {
        cudaDeviceGetAttribute(&sms, cudaDevAttrMultiProcessorCount, 0);
        cudaFuncSetAttribute(main_kernel, cudaFuncAttributeMaxDynamicSharedMemorySize, SMEM_BYTES);
    }

    fold_kernel<<<1, 128>>>(m1w, m1b, m2w, m2b, m3aw, m3ab);
    proj_kernel<<<(N + 31) / 32, 256>>>(x, W, N);
    main_kernel<<<sms, 256, SMEM_BYTES>>>(xyz, knn, m1w, m1b, m3aw, m3bw, m3bb, N);
    bn_partial_kernel<<<PB, C>>>(N);
    bn_final_kernel<<<1, C>>>(gamma, beta, N);
    int total4 = N * (C / 4);
    bn_apply_kernel<<<(total4 + 255) / 256, 256>>>((float*)d_out, N);
}

// round 5
// speedup vs baseline: 2.5836x; 2.5773x over previous
#include <cuda_runtime.h>
#include <cuda_bf16.h>
#include <math.h>

#define KNN_K 16
#define C 128
#define D2 64
#define EPS 1e-5f
#define NMAX 100000
#define PB 256

// ---------------- scratch ----------------
__device__ float g_xp[NMAX * C];
__device__ float g_xsmax[NMAX * C];
__device__ float g_M[3 * C];
__device__ float g_cvec[C];
__device__ float g_part[PB * C];
__device__ float g_partsq[PB * C];
__device__ __align__(16) float g_scale[C];
__device__ __align__(16) float g_shift[C];

__device__ __forceinline__ float gelu_exact(float x) {
    return 0.5f * x * (1.0f + erff(x * 0.7071067811865476f));
}
__device__ __forceinline__ unsigned long long dup2(float v) {
    unsigned long long r;
    asm("mov.b64 %0, {%1, %1};" : "=l"(r) : "f"(v));
    return r;
}
__device__ __forceinline__ void unpack2(unsigned long long v, float& lo, float& hi) {
    asm("mov.b64 {%0, %1}, %2;" : "=f"(lo), "=f"(hi) : "l"(v));
}
__device__ __forceinline__ void fma2(unsigned long long& a, unsigned long long h,
                                     unsigned long long w) {
    asm("fma.rn.f32x2 %0, %1, %2, %0;" : "+l"(a) : "l"(h), "l"(w));
}

// ---------------- kernel 0: fold affine chain ----------------
__global__ void fold_kernel(const float* __restrict__ m1w, const float* __restrict__ m1b,
                            const float* __restrict__ m2w, const float* __restrict__ m2b,
                            const float* __restrict__ m3aw, const float* __restrict__ m3ab) {
    __shared__ float T[3 * D2];
    __shared__ float U[D2];
    int tid = threadIdx.x;
    for (int idx = tid; idx < 3 * D2; idx += blockDim.x) {
        int d = idx / D2, b = idx % D2;
        float s = 0.f;
        for (int a = 0; a < D2; a++) s = fmaf(m1w[d * D2 + a], m2w[a * D2 + b], s);
        T[idx] = s;
    }
    if (tid < D2) {
        int b = tid;
        float s = m2b[b];
        for (int a = 0; a < D2; a++) s = fmaf(m1b[a], m2w[a * D2 + b], s);
        U[b] = s;
    }
    __syncthreads();
    if (tid < C) {
        int c = tid;
        for (int d = 0; d < 3; d++) {
            float s = 0.f;
            for (int b = 0; b < D2; b++) s = fmaf(T[d * D2 + b], m3aw[b * C + c], s);
            g_M[d * C + c] = s;
        }
        float s = m3ab[c];
        for (int b = 0; b < D2; b++) s = fmaf(U[b], m3aw[b * C + c], s);
        g_cvec[c] = s;
    }
}

// ---------------- kernel 1: xp = x @ W ----------------
__global__ __launch_bounds__(256) void proj_kernel(const float* __restrict__ x,
                                                   const float* __restrict__ W, int N) {
    __shared__ float sXt[C * 36];
    int tid = threadIdx.x;
    int r0 = blockIdx.x * 32;
    for (int idx = tid; idx < 32 * C; idx += 256) {
        int row = idx >> 7, cc = idx & 127;
        int gr = r0 + row; if (gr >= N) gr = N - 1;
        sXt[cc * 36 + row] = x[(size_t)gr * C + cc];
    }
    __syncthreads();
    int c = tid & 127;
    int g = tid >> 7;
    float acc[16];
#pragma unroll
    for (int u = 0; u < 16; u++) acc[u] = 0.f;
#pragma unroll 8
    for (int r = 0; r < C; r++) {
        float w = __ldg(W + r * C + c);
        const float4* xb = (const float4*)(sXt + r * 36 + g * 16);
        float4 a0 = xb[0], a1 = xb[1], a2 = xb[2], a3 = xb[3];
        acc[0]  = fmaf(a0.x, w, acc[0]);  acc[1]  = fmaf(a0.y, w, acc[1]);
        acc[2]  = fmaf(a0.z, w, acc[2]);  acc[3]  = fmaf(a0.w, w, acc[3]);
        acc[4]  = fmaf(a1.x, w, acc[4]);  acc[5]  = fmaf(a1.y, w, acc[5]);
        acc[6]  = fmaf(a1.z, w, acc[6]);  acc[7]  = fmaf(a1.w, w, acc[7]);
        acc[8]  = fmaf(a2.x, w, acc[8]);  acc[9]  = fmaf(a2.y, w, acc[9]);
        acc[10] = fmaf(a2.z, w, acc[10]); acc[11] = fmaf(a2.w, w, acc[11]);
        acc[12] = fmaf(a3.x, w, acc[12]); acc[13] = fmaf(a3.y, w, acc[13]);
        acc[14] = fmaf(a3.z, w, acc[14]); acc[15] = fmaf(a3.w, w, acc[15]);
    }
#pragma unroll
    for (int u = 0; u < 16; u++) {
        int rr = r0 + g * 16 + u;
        if (rr < N) g_xp[(size_t)rr * C + c] = acc[u];
    }
}

// ---------------- kernel 2: warp-per-point fused edge MLP + max ----------------
// smem float offsets
#define OFF_W    0                    // 16384: m3b [r][c]
#define OFF_A3   16384                // 8192:  m3a rows 64..127 [d][r]
#define OFF_HT   24576                // 8 warps * 2048: h transposed, row=16 floats,
                                      //   float s in row r is h[k] with s=2*(k&7)+(k>>3)
#define OFF_BASE (OFF_HT + 16384)     // 8 * 128
#define OFF_PL   (OFF_BASE + 1024)    // 8 * 64
#define OFF_DX   (OFF_PL + 512)       // 8 * 16
#define OFF_DY   (OFF_DX + 128)
#define OFF_DZ   (OFF_DY + 128)
#define OFF_JN   (OFF_DZ + 128)       // 8 * 16 ints
#define OFF_M    (OFF_JN + 128)       // 384
#define OFF_CV   (OFF_M + 384)        // 128
#define OFF_M1   (OFF_CV + 128)       // 192
#define OFF_M1B  (OFF_M1 + 192)       // 64
#define OFF_B3B  (OFF_M1B + 64)       // 128
#define SMEM_FLOATS (OFF_B3B + 128)
#define SMEM_BYTES (SMEM_FLOATS * 4)

__global__ __launch_bounds__(256, 1) void main_kernel(
    const float* __restrict__ xyz, const int* __restrict__ knn,
    const float* __restrict__ m1w, const float* __restrict__ m1b,
    const float* __restrict__ m3aw, const float* __restrict__ m3bw,
    const float* __restrict__ m3bb, int N) {
    extern __shared__ float smem[];
    float* sW   = smem + OFF_W;
    float* sA3  = smem + OFF_A3;
    float* sM   = smem + OFF_M;
    float* sCv  = smem + OFF_CV;
    float* sM1  = smem + OFF_M1;
    float* sM1b = smem + OFF_M1B;
    float* sB3b = smem + OFF_B3B;

    const int tid = threadIdx.x;
    const int wid = tid >> 5;
    const int lane = tid & 31;

    // per-warp regions
    float* sHt   = smem + OFF_HT + wid * 2048;
    float* sBase = smem + OFF_BASE + wid * 128;
    float* sPl   = smem + OFF_PL + wid * 64;
    float* sDx   = smem + OFF_DX + wid * 16;
    float* sDy   = smem + OFF_DY + wid * 16;
    float* sDz   = smem + OFF_DZ + wid * 16;
    int*   sJn   = (int*)(smem + OFF_JN) + wid * 16;

    // stage shared weights once
    for (int idx = tid; idx < C * C; idx += 256) sW[idx] = __ldg(m3bw + idx);
    for (int idx = tid; idx < D2 * C; idx += 256) sA3[idx] = __ldg(m3aw + D2 * C + idx);
    for (int idx = tid; idx < 3 * C; idx += 256) sM[idx] = g_M[idx];
    for (int idx = tid; idx < C; idx += 256) { sCv[idx] = g_cvec[idx]; sB3b[idx] = m3bb[idx]; }
    for (int idx = tid; idx < 3 * D2; idx += 256) sM1[idx] = m1w[idx];
    for (int idx = tid; idx < D2; idx += 256) sM1b[idx] = m1b[idx];
    __syncthreads();

    const int gw = blockIdx.x * 8 + wid;
    const int nwarps = gridDim.x * 8;
    const int c0 = lane * 4;

    for (int i = gw; i < N; i += nwarps) {
        // ---- phase a: knn indices + xyz deltas ----
        if (lane < KNN_K) {
            int k = lane;
            int j = __ldg(knn + (size_t)i * KNN_K + k);
            sJn[k] = j;
            float cx = __ldg(xyz + (size_t)i * 3 + 0);
            float cy = __ldg(xyz + (size_t)i * 3 + 1);
            float cz = __ldg(xyz + (size_t)i * 3 + 2);
            sDx[k] = __ldg(xyz + (size_t)j * 3 + 0) - cx;
            sDy[k] = __ldg(xyz + (size_t)j * 3 + 1) - cy;
            sDz[k] = __ldg(xyz + (size_t)j * 3 + 2) - cz;
        }
        float4 xpi = *(const float4*)(g_xp + (size_t)i * C + c0);
        __syncwarp();

        // ---- phase b: p_local (2 d per lane) ----
#pragma unroll
        for (int hh = 0; hh < 2; hh++) {
            int d = lane + hh * 32;
            float w0 = sM1[d], w1 = sM1[D2 + d], w2 = sM1[2 * D2 + d], b = sM1b[d];
            float pl = -3.4e38f;
#pragma unroll
            for (int k = 0; k < KNN_K; k++) {
                float v = fmaf(sDx[k], w0, fmaf(sDy[k], w1, fmaf(sDz[k], w2, b)));
                pl = fmaxf(pl, v);
            }
            sPl[d] = pl;
        }
        __syncwarp();

        // ---- base[r] = cvec[r] + pl . A3[:,r]  (r-quad per lane) ----
        {
            float4 b4 = *(const float4*)(sCv + c0);
#pragma unroll 8
            for (int d = 0; d < D2; d++) {
                float pd = sPl[d];
                float4 a = *(const float4*)(sA3 + d * C + c0);
                b4.x = fmaf(pd, a.x, b4.x);
                b4.y = fmaf(pd, a.y, b4.y);
                b4.z = fmaf(pd, a.z, b4.z);
                b4.w = fmaf(pd, a.w, b4.w);
            }
            *(float4*)(sBase + c0) = b4;
        }
        __syncwarp();

        // ---- phase c: h[k][r] = gelu(base[r] + d.M[:,r]), transposed+interleaved ----
        {
            int k = lane & 15;
            int rh = lane >> 4;       // r half
            int s = 2 * (k & 7) + (k >> 3);
            float dx = sDx[k], dy = sDy[k], dz = sDz[k];
            float* hb = sHt + s;
#pragma unroll 4
            for (int rr = 0; rr < 64; rr++) {
                int r = rh * 64 + rr;
                float pre = sBase[r] + fmaf(dx, sM[r],
                             fmaf(dy, sM[C + r], dz * sM[2 * C + r]));
                hb[r * 16] = gelu_exact(pre);
            }
        }
        __syncwarp();

        // ---- phase d: pe = h @ W3b, register-tiled 16k x 4c per lane ----
        unsigned long long acc[8][4];
#pragma unroll
        for (int m = 0; m < 8; m++)
#pragma unroll
            for (int q = 0; q < 4; q++) acc[m][q] = 0ull;

#pragma unroll 2
        for (int r = 0; r < C; r++) {
            const ulonglong2* hp = (const ulonglong2*)(sHt + r * 16);
            ulonglong2 h01 = hp[0], h23 = hp[1], h45 = hp[2], h67 = hp[3];
            float4 w4 = *(const float4*)(sW + r * C + c0);
            unsigned long long wd0 = dup2(w4.x), wd1 = dup2(w4.y);
            unsigned long long wd2 = dup2(w4.z), wd3 = dup2(w4.w);
            unsigned long long hm[8] = {h01.x, h01.y, h23.x, h23.y,
                                        h45.x, h45.y, h67.x, h67.y};
#pragma unroll
            for (int m = 0; m < 8; m++) {
                fma2(acc[m][0], hm[m], wd0);
                fma2(acc[m][1], hm[m], wd1);
                fma2(acc[m][2], hm[m], wd2);
                fma2(acc[m][3], hm[m], wd3);
            }
        }

        // ---- epilogue: add neighbor gather, max over k, subtract center ----
        float rm0 = -3.4e38f, rm1 = -3.4e38f, rm2 = -3.4e38f, rm3 = -3.4e38f;
#pragma unroll
        for (int m = 0; m < 8; m++) {
            int j0 = sJn[m], j1 = sJn[m + 8];
            float4 g0 = *(const float4*)(g_xp + (size_t)j0 * C + c0);
            float4 g1 = *(const float4*)(g_xp + (size_t)j1 * C + c0);
            float lo, hi;
            unpack2(acc[m][0], lo, hi);
            rm0 = fmaxf(rm0, fmaxf(lo + g0.x, hi + g1.x));
            unpack2(acc[m][1], lo, hi);
            rm1 = fmaxf(rm1, fmaxf(lo + g0.y, hi + g1.y));
            unpack2(acc[m][2], lo, hi);
            rm2 = fmaxf(rm2, fmaxf(lo + g0.z, hi + g1.z));
            unpack2(acc[m][3], lo, hi);
            rm3 = fmaxf(rm3, fmaxf(lo + g0.w, hi + g1.w));
        }
        float4 o;
        o.x = rm0 + sB3b[c0 + 0] - xpi.x;
        o.y = rm1 + sB3b[c0 + 1] - xpi.y;
        o.z = rm2 + sB3b[c0 + 2] - xpi.z;
        o.w = rm3 + sB3b[c0 + 3] - xpi.w;
        *(float4*)(g_xsmax + (size_t)i * C + c0) = o;
        __syncwarp();
    }
}

// ---------------- kernel 3: BatchNorm ----------------
__global__ void bn_partial_kernel(int N) {
    int c = threadIdx.x;
    int rpb = (N + PB - 1) / PB;
    int r0 = blockIdx.x * rpb;
    int r1 = min(N, r0 + rpb);
    float s = 0.f, q = 0.f;
    for (int r = r0; r < r1; r++) {
        float v = g_xsmax[(size_t)r * C + c];
        s += v;
        q = fmaf(v, v, q);
    }
    g_part[blockIdx.x * C + c] = s;
    g_partsq[blockIdx.x * C + c] = q;
}

__global__ void bn_final_kernel(const float* __restrict__ gamma, const float* __restrict__ beta, int N) {
    int c = threadIdx.x;
    float s = 0.f, q = 0.f;
    for (int b = 0; b < PB; b++) { s += g_part[b * C + c]; q += g_partsq[b * C + c]; }
    float mean = s / (float)N;
    float var = q / (float)N - mean * mean;
    if (var < 0.f) var = 0.f;
    float sc = rsqrtf(var + EPS) * gamma[c];
    g_scale[c] = sc;
    g_shift[c] = beta[c] - mean * sc;
}

__global__ void bn_apply_kernel(float* __restrict__ out, int N) {
    int idx = blockIdx.x * blockDim.x + threadIdx.x;
    int total4 = N * (C / 4);
    if (idx >= total4) return;
    float4 v = ((const float4*)g_xsmax)[idx];
    int c4 = idx & 31;
    float4 sc = ((const float4*)g_scale)[c4];
    float4 sf = ((const float4*)g_shift)[c4];
    float4 o;
    o.x = fmaf(v.x, sc.x, sf.x);
    o.y = fmaf(v.y, sc.y, sf.y);
    o.z = fmaf(v.z, sc.z, sf.z);
    o.w = fmaf(v.w, sc.w, sf.w);
    ((float4*)out)[idx] = o;
}

// ---------------- launch ----------------
extern "C" void kernel_launch(void* const* d_in, const int* in_sizes, int n_in,
                              void* d_out, int out_size) {
    const float* xyz  = (const float*)d_in[0];
    const float* x    = (const float*)d_in[1];
    const int*   knn  = (const int*)d_in[2];
    const float* W    = (const float*)d_in[3];
    const float* m1w  = (const float*)d_in[4];
    const float* m1b  = (const float*)d_in[5];
    const float* m2w  = (const float*)d_in[6];
    const float* m2b  = (const float*)d_in[7];
    const float* m3aw = (const float*)d_in[8];
    const float* m3ab = (const float*)d_in[9];
    const float* m3bw = (const float*)d_in[10];
    const float* m3bb = (const float*)d_in[11];
    const float* gamma = (const float*)d_in[12];
    const float* beta  = (const float*)d_in[13];

    int N = in_sizes[0] / 3;

    static int sms = 0;
    if (sms == 0) {
        cudaDeviceGetAttribute(&sms, cudaDevAttrMultiProcessorCount, 0);
        cudaFuncSetAttribute(main_kernel, cudaFuncAttributeMaxDynamicSharedMemorySize, SMEM_BYTES);
    }

    fold_kernel<<<1, 128>>>(m1w, m1b, m2w, m2b, m3aw, m3ab);
    proj_kernel<<<(N + 31) / 32, 256>>>(x, W, N);
    main_kernel<<<sms, 256, SMEM_BYTES>>>(xyz, knn, m1w, m1b, m3aw, m3bw, m3bb, N);
    bn_partial_kernel<<<PB, C>>>(N);
    bn_final_kernel<<<1, C>>>(gamma, beta, N);
    int total4 = N * (C / 4);
    bn_apply_kernel<<<(total4 + 255) / 256, 256>>>((float*)d_out, N);
}

// round 12
// speedup vs baseline: 2.7604x; 1.0684x over previous
#include <cuda_runtime.h>
#include <cuda_bf16.h>
#include <math.h>
#include <stdint.h>

#define KNN_K 16
#define C 128
#define D2 64
#define EPS 1e-5f
#define NMAX 100000
#define PB 256
#define GRP 8

__device__ float g_xp[NMAX * C];
__device__ float g_xsmax[NMAX * C];
__device__ float g_M[3 * C];
__device__ float g_cvec[C];
__device__ float g_part[PB * C];
__device__ float g_partsq[PB * C];
__device__ __align__(16) float g_scale[C];
__device__ __align__(16) float g_shift[C];

__device__ __forceinline__ float gelu_exact(float x) {
    return 0.5f * x * (1.0f + erff(x * 0.7071067811865476f));
}
__device__ __forceinline__ uint32_t f2tf32(float f) {
    uint32_t u;
    asm("cvt.rna.tf32.f32 %0, %1;" : "=r"(u) : "f"(f));
    return u;
}
__device__ __forceinline__ void mma8(float* c, const uint4 a, const uint2 b) {
    asm volatile(
        "mma.sync.aligned.m16n8k8.row.col.f32.tf32.tf32.f32 "
        "{%0,%1,%2,%3}, {%4,%5,%6,%7}, {%8,%9}, {%0,%1,%2,%3};"
        : "+f"(c[0]), "+f"(c[1]), "+f"(c[2]), "+f"(c[3])
        : "r"(a.x), "r"(a.y), "r"(a.z), "r"(a.w), "r"(b.x), "r"(b.y));
}

// ---------------- kernel 0: fold affine chain ----------------
__global__ void fold_kernel(const float* __restrict__ m1w, const float* __restrict__ m1b,
                            const float* __restrict__ m2w, const float* __restrict__ m2b,
                            const float* __restrict__ m3aw, const float* __restrict__ m3ab) {
    __shared__ float T[3 * D2];
    __shared__ float U[D2];
    int tid = threadIdx.x;
    for (int idx = tid; idx < 3 * D2; idx += blockDim.x) {
        int d = idx / D2, b = idx % D2;
        float s = 0.f;
        for (int a = 0; a < D2; a++) s = fmaf(m1w[d * D2 + a], m2w[a * D2 + b], s);
        T[idx] = s;
    }
    if (tid < D2) {
        int b = tid;
        float s = m2b[b];
        for (int a = 0; a < D2; a++) s = fmaf(m1b[a], m2w[a * D2 + b], s);
        U[b] = s;
    }
    __syncthreads();
    if (tid < C) {
        int c = tid;
        for (int d = 0; d < 3; d++) {
            float s = 0.f;
            for (int b = 0; b < D2; b++) s = fmaf(T[d * D2 + b], m3aw[b * C + c], s);
            g_M[d * C + c] = s;
        }
        float s = m3ab[c];
        for (int b = 0; b < D2; b++) s = fmaf(U[b], m3aw[b * C + c], s);
        g_cvec[c] = s;
    }
}

// ---------------- kernel 1: xp = x @ W ----------------
__global__ __launch_bounds__(256) void proj_kernel(const float* __restrict__ x,
                                                   const float* __restrict__ W, int N) {
    __shared__ float sXt[C * 36];
    int tid = threadIdx.x;
    int r0 = blockIdx.x * 32;
    for (int idx = tid; idx < 32 * C; idx += 256) {
        int row = idx >> 7, cc = idx & 127;
        int gr = r0 + row; if (gr >= N) gr = N - 1;
        sXt[cc * 36 + row] = x[(size_t)gr * C + cc];
    }
    __syncthreads();
    int c = tid & 127;
    int g = tid >> 7;
    float acc[16];
#pragma unroll
    for (int u = 0; u < 16; u++) acc[u] = 0.f;
#pragma unroll 8
    for (int r = 0; r < C; r++) {
        float w = __ldg(W + r * C + c);
        const float4* xb = (const float4*)(sXt + r * 36 + g * 16);
        float4 a0 = xb[0], a1 = xb[1], a2 = xb[2], a3 = xb[3];
        acc[0]  = fmaf(a0.x, w, acc[0]);  acc[1]  = fmaf(a0.y, w, acc[1]);
        acc[2]  = fmaf(a0.z, w, acc[2]);  acc[3]  = fmaf(a0.w, w, acc[3]);
        acc[4]  = fmaf(a1.x, w, acc[4]);  acc[5]  = fmaf(a1.y, w, acc[5]);
        acc[6]  = fmaf(a1.z, w, acc[6]);  acc[7]  = fmaf(a1.w, w, acc[7]);
        acc[8]  = fmaf(a2.x, w, acc[8]);  acc[9]  = fmaf(a2.y, w, acc[9]);
        acc[10] = fmaf(a2.z, w, acc[10]); acc[11] = fmaf(a2.w, w, acc[11]);
        acc[12] = fmaf(a3.x, w, acc[12]); acc[13] = fmaf(a3.y, w, acc[13]);
        acc[14] = fmaf(a3.z, w, acc[14]); acc[15] = fmaf(a3.w, w, acc[15]);
    }
#pragma unroll
    for (int u = 0; u < 16; u++) {
        int rr = r0 + g * 16 + u;
        if (rr < N) g_xp[(size_t)rr * C + c] = acc[u];
    }
}

// ---------------- kernel 2: mma.sync tf32 fused edge MLP + max ----------------
#define OFF_BP   0
#define OFF_AP   16384
#define OFF_A3   32768
#define OFF_BASE 40960
#define OFF_PL   41984
#define OFF_DX   42496
#define OFF_DY   42624
#define OFF_DZ   42752
#define OFF_JN   42880
#define OFF_M    43008
#define OFF_CV   43392
#define OFF_M1   43520
#define OFF_M1B  43712
#define OFF_B3B  43776
#define SMEM_FLOATS 43904
#define SMEM_BYTES (SMEM_FLOATS * 4)

__global__ __launch_bounds__(256, 1) void main_kernel(
    const float* __restrict__ xyz, const int* __restrict__ knn,
    const float* __restrict__ m1w, const float* __restrict__ m1b,
    const float* __restrict__ m3aw, const float* __restrict__ m3bw,
    const float* __restrict__ m3bb, int N) {
    extern __shared__ float smem[];
    uint32_t* sApU = (uint32_t*)(smem + OFF_AP);
    uint2*    sBp2 = (uint2*)(smem + OFF_BP);
    uint4*    sAp4 = (uint4*)(smem + OFF_AP);
    float* sA3  = smem + OFF_A3;
    float* sBase= smem + OFF_BASE;
    float* sPl  = smem + OFF_PL;
    float* sDx  = smem + OFF_DX;
    float* sDy  = smem + OFF_DY;
    float* sDz  = smem + OFF_DZ;
    int*   sJn  = (int*)(smem + OFF_JN);
    float* sM   = smem + OFF_M;
    float* sCv  = smem + OFF_CV;
    float* sM1  = smem + OFF_M1;
    float* sM1b = smem + OFF_M1B;
    float* sB3b = smem + OFF_B3B;

    const int tid = threadIdx.x;
    const int wid = tid >> 5;
    const int lane = tid & 31;

    // stage Bpack: frag (nt, kk, lane): b0=W[8kk+tg][8nt+gg], b1=W[8kk+tg+4][8nt+gg]
    for (int idx = tid; idx < 8192; idx += 256) {
        int nt = idx >> 9, kk = (idx >> 5) & 15, l = idx & 31;
        int gg = l >> 2, tg = l & 3;
        uint2 bb;
        bb.x = f2tf32(__ldg(m3bw + (8 * kk + tg) * C + 8 * nt + gg));
        bb.y = f2tf32(__ldg(m3bw + (8 * kk + tg + 4) * C + 8 * nt + gg));
        sBp2[idx] = bb;
    }
    for (int idx = tid; idx < D2 * C; idx += 256) sA3[idx] = __ldg(m3aw + D2 * C + idx);
    for (int idx = tid; idx < 3 * C; idx += 256) sM[idx] = g_M[idx];
    for (int idx = tid; idx < C; idx += 256) { sCv[idx] = g_cvec[idx]; sB3b[idx] = __ldg(m3bb + idx); }
    for (int idx = tid; idx < 3 * D2; idx += 256) sM1[idx] = __ldg(m1w + idx);
    for (int idx = tid; idx < D2; idx += 256) sM1b[idx] = __ldg(m1b + idx);
    __syncthreads();

    const int mhalf = wid >> 2;
    const int nquad = wid & 3;
    const int fg = lane >> 2;
    const int ftg = lane & 3;
    const int ngroups = (N + GRP - 1) / GRP;

    for (int g = blockIdx.x; g < ngroups; g += gridDim.x) {
        const int p = wid;
        int i = g * GRP + p;
        if (i >= N) i = N - 1;

        // ---- phase a: knn + deltas ----
        if (lane < KNN_K) {
            int k = lane;
            int j = __ldg(knn + (size_t)i * KNN_K + k);
            sJn[p * KNN_K + k] = j;
            float cx = __ldg(xyz + (size_t)i * 3 + 0);
            float cy = __ldg(xyz + (size_t)i * 3 + 1);
            float cz = __ldg(xyz + (size_t)i * 3 + 2);
            sDx[p * KNN_K + k] = __ldg(xyz + (size_t)j * 3 + 0) - cx;
            sDy[p * KNN_K + k] = __ldg(xyz + (size_t)j * 3 + 1) - cy;
            sDz[p * KNN_K + k] = __ldg(xyz + (size_t)j * 3 + 2) - cz;
        }
        __syncwarp();

        // ---- phase b: p_local ----
#pragma unroll
        for (int hh = 0; hh < 2; hh++) {
            int d = lane + hh * 32;
            float w0 = sM1[d], w1 = sM1[D2 + d], w2 = sM1[2 * D2 + d], b = sM1b[d];
            float pl = -3.4e38f;
#pragma unroll
            for (int k = 0; k < KNN_K; k++) {
                float v = fmaf(sDx[p * KNN_K + k], w0,
                          fmaf(sDy[p * KNN_K + k], w1,
                          fmaf(sDz[p * KNN_K + k], w2, b)));
                pl = fmaxf(pl, v);
            }
            sPl[p * D2 + d] = pl;
        }
        __syncwarp();

        // ---- base[r] = cvec[r] + pl . a3[:,r] ----
        {
            int c0 = lane * 4;
            float4 b4 = *(const float4*)(sCv + c0);
#pragma unroll 8
            for (int d = 0; d < D2; d++) {
                float pd = sPl[p * D2 + d];
                float4 a = *(const float4*)(sA3 + d * C + c0);
                b4.x = fmaf(pd, a.x, b4.x);
                b4.y = fmaf(pd, a.y, b4.y);
                b4.z = fmaf(pd, a.z, b4.z);
                b4.w = fmaf(pd, a.w, b4.w);
            }
            *(float4*)(sBase + p * C + c0) = b4;
        }
        __syncwarp();

        // ---- phase c: h[k][r] -> Apack fragments (tf32) ----
        {
            int k = lane & 15;
            int rh = lane >> 4;
            float dx = sDx[p * KNN_K + k];
            float dy = sDy[p * KNN_K + k];
            float dz = sDz[p * KNN_K + k];
            int gg = k & 7, hrow = k >> 3;
            uint32_t* apb = sApU + p * 2048;
#pragma unroll 8
            for (int rr = 0; rr < 64; rr++) {
                int r = rh * 64 + rr;
                float pre = sBase[p * C + r] +
                            fmaf(dx, sM[r], fmaf(dy, sM[C + r], dz * sM[2 * C + r]));
                int kk = r >> 3, tg = r & 3, ch = (r >> 2) & 1;
                apb[kk * 128 + (gg * 4 + tg) * 4 + ch * 2 + hrow] = f2tf32(gelu_exact(pre));
            }
        }
        __syncthreads();

        // ---- MMA: 64x32 tile per warp ----
        float acc[4][4][4];
#pragma unroll
        for (int mt = 0; mt < 4; mt++)
#pragma unroll
            for (int nt = 0; nt < 4; nt++)
#pragma unroll
                for (int q = 0; q < 4; q++) acc[mt][nt][q] = 0.f;

#pragma unroll 4
        for (int kk = 0; kk < 16; kk++) {
            uint4 Af[4];
            uint2 Bf[4];
#pragma unroll
            for (int mt = 0; mt < 4; mt++)
                Af[mt] = sAp4[((mhalf * 4 + mt) * 16 + kk) * 32 + lane];
#pragma unroll
            for (int nt = 0; nt < 4; nt++)
                Bf[nt] = sBp2[((nquad * 4 + nt) * 16 + kk) * 32 + lane];
#pragma unroll
            for (int mt = 0; mt < 4; mt++)
#pragma unroll
                for (int nt = 0; nt < 4; nt++)
                    mma8(acc[mt][nt], Af[mt], Bf[nt]);
        }

        // ---- epilogue: + gather, max over k, store ----
#pragma unroll
        for (int mt = 0; mt < 4; mt++) {
            const int pp = mhalf * 4 + mt;
            const int ip = g * GRP + pp;
            const int j0 = sJn[pp * KNN_K + fg];
            const int j1 = sJn[pp * KNN_K + 8 + fg];
#pragma unroll
            for (int nt = 0; nt < 4; nt++) {
                const int c = 8 * (nquad * 4 + nt) + 2 * ftg;
                float2 ga = *(const float2*)(g_xp + (size_t)j0 * C + c);
                float2 gb = *(const float2*)(g_xp + (size_t)j1 * C + c);
                float v0 = fmaxf(acc[mt][nt][0] + ga.x, acc[mt][nt][2] + gb.x);
                float v1 = fmaxf(acc[mt][nt][1] + ga.y, acc[mt][nt][3] + gb.y);
#pragma unroll
                for (int s = 4; s <= 16; s <<= 1) {
                    v0 = fmaxf(v0, __shfl_xor_sync(0xffffffffu, v0, s));
                    v1 = fmaxf(v1, __shfl_xor_sync(0xffffffffu, v1, s));
                }
                if (fg == 0 && ip < N) {
                    float2 xc = *(const float2*)(g_xp + (size_t)ip * C + c);
                    float2 o;
                    o.x = v0 + sB3b[c] - xc.x;
                    o.y = v1 + sB3b[c + 1] - xc.y;
                    *(float2*)(g_xsmax + (size_t)ip * C + c) = o;
                }
            }
        }
        __syncthreads();
    }
}

// ---------------- kernel 3: BatchNorm ----------------
__global__ void bn_partial_kernel(int N) {
    int c = threadIdx.x;
    int rpb = (N + PB - 1) / PB;
    int r0 = blockIdx.x * rpb;
    int r1 = min(N, r0 + rpb);
    float s = 0.f, q = 0.f;
    for (int r = r0; r < r1; r++) {
        float v = g_xsmax[(size_t)r * C + c];
        s += v;
        q = fmaf(v, v, q);
    }
    g_part[blockIdx.x * C + c] = s;
    g_partsq[blockIdx.x * C + c] = q;
}

__global__ void bn_final_kernel(const float* __restrict__ gamma, const float* __restrict__ beta, int N) {
    int c = threadIdx.x;
    float s = 0.f, q = 0.f;
    for (int b = 0; b < PB; b++) { s += g_part[b * C + c]; q += g_partsq[b * C + c]; }
    float mean = s / (float)N;
    float var = q / (float)N - mean * mean;
    if (var < 0.f) var = 0.f;
    float sc = rsqrtf(var + EPS) * gamma[c];
    g_scale[c] = sc;
    g_shift[c] = beta[c] - mean * sc;
}

__global__ void bn_apply_kernel(float* __restrict__ out, int N) {
    int idx = blockIdx.x * blockDim.x + threadIdx.x;
    int total4 = N * (C / 4);
    if (idx >= total4) return;
    float4 v = ((const float4*)g_xsmax)[idx];
    int c4 = idx & 31;
    float4 sc = ((const float4*)g_scale)[c4];
    float4 sf = ((const float4*)g_shift)[c4];
    float4 o;
    o.x = fmaf(v.x, sc.x, sf.x);
    o.y = fmaf(v.y, sc.y, sf.y);
    o.z = fmaf(v.z, sc.z, sf.z);
    o.w = fmaf(v.w, sc.w, sf.w);
    ((float4*)out)[idx] = o;
}

// ---------------- launch ----------------
extern "C" void kernel_launch(void* const* d_in, const int* in_sizes, int n_in,
                              void* d_out, int out_size) {
    const float* xyz  = (const float*)d_in[0];
    const float* x    = (const float*)d_in[1];
    const int*   knn  = (const int*)d_in[2];
    const float* W    = (const float*)d_in[3];
    const float* m1w  = (const float*)d_in[4];
    const float* m1b  = (const float*)d_in[5];
    const float* m2w  = (const float*)d_in[6];
    const float* m2b  = (const float*)d_in[7];
    const float* m3aw = (const float*)d_in[8];
    const float* m3ab = (const float*)d_in[9];
    const float* m3bw = (const float*)d_in[10];
    const float* m3bb = (const float*)d_in[11];
    const float* gamma = (const float*)d_in[12];
    const float* beta  = (const float*)d_in[13];

    int N = in_sizes[0] / 3;

    static int sms = 0;
    if (sms == 0) {
        cudaDeviceGetAttribute(&sms, cudaDevAttrMultiProcessorCount, 0);
        cudaFuncSetAttribute(main_kernel, cudaFuncAttributeMaxDynamicSharedMemorySize, SMEM_BYTES);
    }

    fold_kernel<<<1, 128>>>(m1w, m1b, m2w, m2b, m3aw, m3ab);
    proj_kernel<<<(N + 31) / 32, 256>>>(x, W, N);
    main_kernel<<<sms, 256, SMEM_BYTES>>>(xyz, knn, m1w, m1b, m3aw, m3bw, m3bb, N);
    bn_partial_kernel<<<PB, C>>>(N);
    bn_final_kernel<<<1, C>>>(gamma, beta, N);
    int total4 = N * (C / 4);
    bn_apply_kernel<<<(total4 + 255) / 256, 256>>>((float*)d_out, N);
}

// round 17
// speedup vs baseline: 4.2725x; 1.5478x over previous
#include <cuda_runtime.h>
#include <cuda_bf16.h>
#include <math.h>
#include <stdint.h>

#define KNN_K 16
#define C 128
#define D2 64
#define EPS 1e-5f
#define NMAX 100000
#define PB 256
#define GRP 16
#define NTHR 512

__device__ float g_xp[NMAX * C];
__device__ float g_xsmax[NMAX * C];
__device__ float g_M[3 * C];
__device__ float g_cvec[C];
__device__ uint2 g_bpA3[16 * 9 * 32];   // base-gemm B fragments (A3ext, tf32)
__device__ float g_part[PB * C];
__device__ float g_partsq[PB * C];
__device__ __align__(16) float g_scale[C];
__device__ __align__(16) float g_shift[C];

__device__ __forceinline__ uint32_t f2tf32(float f) {
    uint32_t u;
    asm("cvt.rna.tf32.f32 %0, %1;" : "=r"(u) : "f"(f));
    return u;
}
// AS 7.1.25 erf (abs err <= 2.5e-5), exp-based; exact-path gelu
__device__ __forceinline__ float gelu_fast(float x) {
    float z = x * 0.70710678f;
    float s = fabsf(z);
    float w = fmaf(0.47047f, s, 1.0f);
    float t;
    asm("rcp.approx.f32 %0, %1;" : "=f"(t) : "f"(w));
    float e = __expf(-z * z);
    float poly = t * fmaf(t, fmaf(t, 0.7478556f, -0.0958798f), 0.3480242f);
    float erfa = fmaf(-poly, e, 1.0f);
    float erfv = copysignf(erfa, z);
    return 0.5f * x * (1.0f + erfv);
}
__device__ __forceinline__ void mma8(float* c, const uint4 a, const uint2 b) {
    asm volatile(
        "mma.sync.aligned.m16n8k8.row.col.f32.tf32.tf32.f32 "
        "{%0,%1,%2,%3}, {%4,%5,%6,%7}, {%8,%9}, {%0,%1,%2,%3};"
        : "+f"(c[0]), "+f"(c[1]), "+f"(c[2]), "+f"(c[3])
        : "r"(a.x), "r"(a.y), "r"(a.z), "r"(a.w), "r"(b.x), "r"(b.y));
}

// ---------------- kernel 0: fold affine chain + pack base-gemm B frags ----------------
__global__ void fold_kernel(const float* __restrict__ m1w, const float* __restrict__ m1b,
                            const float* __restrict__ m2w, const float* __restrict__ m2b,
                            const float* __restrict__ m3aw, const float* __restrict__ m3ab) {
    __shared__ float T[3 * D2];
    __shared__ float U[D2];
    int tid = threadIdx.x;
    for (int idx = tid; idx < 3 * D2; idx += blockDim.x) {
        int d = idx / D2, b = idx % D2;
        float s = 0.f;
        for (int a = 0; a < D2; a++) s = fmaf(m1w[d * D2 + a], m2w[a * D2 + b], s);
        T[idx] = s;
    }
    if (tid < D2) {
        int b = tid;
        float s = m2b[b];
        for (int a = 0; a < D2; a++) s = fmaf(m1b[a], m2w[a * D2 + b], s);
        U[b] = s;
    }
    __syncthreads();
    if (tid < C) {
        int c = tid;
        for (int d = 0; d < 3; d++) {
            float s = 0.f;
            for (int b = 0; b < D2; b++) s = fmaf(T[d * D2 + b], m3aw[b * C + c], s);
            g_M[d * C + c] = s;
        }
        float s = m3ab[c];
        for (int b = 0; b < D2; b++) s = fmaf(U[b], m3aw[b * C + c], s);
        g_cvec[c] = s;
    }
    __syncthreads();
    // pack A3ext fragments: A3e[d][r] = m3a[64+d][r] (d<64), A3e[64][r]=cvec[r], else 0
    for (int idx = tid; idx < 16 * 9 * 32; idx += blockDim.x) {
        int nt = idx / (9 * 32), kk = (idx / 32) % 9, l = idx & 31;
        int gg = l >> 2, tg = l & 3;
        int rcol = 8 * nt + gg;
        int d0 = 8 * kk + tg, d1 = d0 + 4;
        float b0 = (d0 < 64) ? m3aw[(size_t)(64 + d0) * C + rcol]
                             : (d0 == 64 ? g_cvec[rcol] : 0.f);
        float b1 = (d1 < 64) ? m3aw[(size_t)(64 + d1) * C + rcol] : 0.f;
        uint2 bb;
        bb.x = f2tf32(b0);
        bb.y = f2tf32(b1);
        g_bpA3[idx] = bb;
    }
}

// ---------------- kernel 1: xp = x @ W ----------------
__global__ __launch_bounds__(256) void proj_kernel(const float* __restrict__ x,
                                                   const float* __restrict__ W, int N) {
    __shared__ float sXt[C * 36];
    int tid = threadIdx.x;
    int r0 = blockIdx.x * 32;
    for (int idx = tid; idx < 32 * C; idx += 256) {
        int row = idx >> 7, cc = idx & 127;
        int gr = r0 + row; if (gr >= N) gr = N - 1;
        sXt[cc * 36 + row] = x[(size_t)gr * C + cc];
    }
    __syncthreads();
    int c = tid & 127;
    int g = tid >> 7;
    float acc[16];
#pragma unroll
    for (int u = 0; u < 16; u++) acc[u] = 0.f;
#pragma unroll 8
    for (int r = 0; r < C; r++) {
        float w = __ldg(W + r * C + c);
        const float4* xb = (const float4*)(sXt + r * 36 + g * 16);
        float4 a0 = xb[0], a1 = xb[1], a2 = xb[2], a3 = xb[3];
        acc[0]  = fmaf(a0.x, w, acc[0]);  acc[1]  = fmaf(a0.y, w, acc[1]);
        acc[2]  = fmaf(a0.z, w, acc[2]);  acc[3]  = fmaf(a0.w, w, acc[3]);
        acc[4]  = fmaf(a1.x, w, acc[4]);  acc[5]  = fmaf(a1.y, w, acc[5]);
        acc[6]  = fmaf(a1.z, w, acc[6]);  acc[7]  = fmaf(a1.w, w, acc[7]);
        acc[8]  = fmaf(a2.x, w, acc[8]);  acc[9]  = fmaf(a2.y, w, acc[9]);
        acc[10] = fmaf(a2.z, w, acc[10]); acc[11] = fmaf(a2.w, w, acc[11]);
        acc[12] = fmaf(a3.x, w, acc[12]); acc[13] = fmaf(a3.y, w, acc[13]);
        acc[14] = fmaf(a3.z, w, acc[14]); acc[15] = fmaf(a3.w, w, acc[15]);
    }
#pragma unroll
    for (int u = 0; u < 16; u++) {
        int rr = r0 + g * 16 + u;
        if (rr < N) g_xp[(size_t)rr * C + c] = acc[u];
    }
}

// ---------------- kernel 2: 512-thr mma.sync fused edge MLP + max ----------------
#define OFF_AP   0          // 32768 floats: A fragments, 16 tiles x 512 uint4
#define OFF_BP   32768      // 16384: B fragments
#define OFF_PLT  49152      // 1024: pl transposed [d][pt]
#define OFF_BASE 50176      // 2048: base [pt][c]
#define OFF_DX   52224      // 256
#define OFF_DY   52480
#define OFF_DZ   52736
#define OFF_JN   52992      // 256 ints
#define OFF_M    53248      // 384
#define OFF_B3B  53632      // 128
#define OFF_M1   53760      // 192
#define OFF_M1B  53952      // 64
#define SMEM_FLOATS 54016
#define SMEM_BYTES (SMEM_FLOATS * 4)

__global__ __launch_bounds__(NTHR, 1) void main_kernel(
    const float* __restrict__ xyz, const int* __restrict__ knn,
    const float* __restrict__ m1w, const float* __restrict__ m1b,
    const float* __restrict__ m3bw, const float* __restrict__ m3bb, int N) {
    extern __shared__ float smem[];
    uint32_t* sApU = (uint32_t*)(smem + OFF_AP);
    uint4*    sAp4 = (uint4*)(smem + OFF_AP);
    uint2*    sBp2 = (uint2*)(smem + OFF_BP);
    float* sPlT = smem + OFF_PLT;
    float* sBase= smem + OFF_BASE;
    float* sDx  = smem + OFF_DX;
    float* sDy  = smem + OFF_DY;
    float* sDz  = smem + OFF_DZ;
    int*   sJn  = (int*)(smem + OFF_JN);
    float* sM   = smem + OFF_M;
    float* sB3b = smem + OFF_B3B;
    float* sM1  = smem + OFF_M1;
    float* sM1b = smem + OFF_M1B;

    const int tid = threadIdx.x;
    const int wid = tid >> 5;
    const int lane = tid & 31;

    // stage main-gemm B fragments + constants
    for (int idx = tid; idx < 8192; idx += NTHR) {
        int nt = idx >> 9, kk = (idx >> 5) & 15, l = idx & 31;
        int gg = l >> 2, tg = l & 3;
        uint2 bb;
        bb.x = f2tf32(__ldg(m3bw + (8 * kk + tg) * C + 8 * nt + gg));
        bb.y = f2tf32(__ldg(m3bw + (8 * kk + tg + 4) * C + 8 * nt + gg));
        sBp2[idx] = bb;
    }
    for (int idx = tid; idx < 3 * C; idx += NTHR) sM[idx] = g_M[idx];
    for (int idx = tid; idx < C; idx += NTHR) sB3b[idx] = __ldg(m3bb + idx);
    for (int idx = tid; idx < 3 * D2; idx += NTHR) sM1[idx] = __ldg(m1w + idx);
    for (int idx = tid; idx < D2; idx += NTHR) sM1b[idx] = __ldg(m1b + idx);
    __syncthreads();

    const int mhalf = wid >> 2;      // 0..3: M-quarter (64 rows)
    const int nquad = wid & 3;       // 0..3: N-quarter (32 cols)
    const int fg = lane >> 2;
    const int ftg = lane & 3;
    const int ngroups = (N + GRP - 1) / GRP;

    for (int g = blockIdx.x; g < ngroups; g += gridDim.x) {
        const int p = wid;           // warp handles point p of group
        int i = g * GRP + p;
        if (i >= N) i = N - 1;

        // ---- phase a: knn + xyz deltas ----
        if (lane < KNN_K) {
            int k = lane;
            int j = __ldg(knn + (size_t)i * KNN_K + k);
            sJn[p * KNN_K + k] = j;
            float cx = __ldg(xyz + (size_t)i * 3 + 0);
            float cy = __ldg(xyz + (size_t)i * 3 + 1);
            float cz = __ldg(xyz + (size_t)i * 3 + 2);
            sDx[p * KNN_K + k] = __ldg(xyz + (size_t)j * 3 + 0) - cx;
            sDy[p * KNN_K + k] = __ldg(xyz + (size_t)j * 3 + 1) - cy;
            sDz[p * KNN_K + k] = __ldg(xyz + (size_t)j * 3 + 2) - cz;
        }
        __syncwarp();

        // ---- phase b: p_local, stored transposed sPlT[d][pt] ----
#pragma unroll
        for (int hh = 0; hh < 2; hh++) {
            int d = lane + hh * 32;
            float w0 = sM1[d], w1 = sM1[D2 + d], w2 = sM1[2 * D2 + d], b = sM1b[d];
            float pl = -3.4e38f;
#pragma unroll
            for (int k = 0; k < KNN_K; k++) {
                float v = fmaf(sDx[p * KNN_K + k], w0,
                          fmaf(sDy[p * KNN_K + k], w1,
                          fmaf(sDz[p * KNN_K + k], w2, b)));
                pl = fmaxf(pl, v);
            }
            sPlT[d * GRP + p] = pl;
        }
        __syncthreads();   // #1: sPlT/sJn visible to all

        // ---- base GEMM: base[16pts][128] = plext @ A3ext (K=72, cvec folded) ----
        {
            float accb[4] = {0.f, 0.f, 0.f, 0.f};
            const int nt = wid;
#pragma unroll
            for (int kk = 0; kk < 9; kk++) {
                uint2 Bf = __ldg(g_bpA3 + (nt * 9 + kk) * 32 + lane);
                uint4 Af;
                if (kk < 8) {
                    Af.x = f2tf32(sPlT[(8 * kk + ftg) * GRP + fg]);
                    Af.y = f2tf32(sPlT[(8 * kk + ftg) * GRP + fg + 8]);
                    Af.z = f2tf32(sPlT[(8 * kk + ftg + 4) * GRP + fg]);
                    Af.w = f2tf32(sPlT[(8 * kk + ftg + 4) * GRP + fg + 8]);
                } else {
                    uint32_t e = (ftg == 0) ? 0x3F800000u : 0u;
                    Af.x = e; Af.y = e; Af.z = 0u; Af.w = 0u;
                }
                mma8(accb, Af, Bf);
            }
            int cb = 8 * nt + 2 * ftg;
            *(float2*)(sBase + fg * C + cb) = make_float2(accb[0], accb[1]);
            *(float2*)(sBase + (fg + 8) * C + cb) = make_float2(accb[2], accb[3]);
        }
        __syncthreads();   // #2: sBase visible

        // ---- phase c: h fragments (lane owns 4 c-cols x 16 k), swizzled store ----
        {
            const int c0 = lane * 4;
            float4 b4 = *(const float4*)(sBase + p * C + c0);
            float4 M0 = *(const float4*)(sM + c0);
            float4 M1 = *(const float4*)(sM + C + c0);
            float4 M2 = *(const float4*)(sM + 2 * C + c0);
            const int swz = (lane >> 1) & 7;
            uint32_t* apb = sApU + p * 2048 + (lane >> 1) * 128 + (lane & 1) * 2;
#pragma unroll
            for (int k = 0; k < KNN_K; k++) {
                float dx = sDx[p * KNN_K + k];
                float dy = sDy[p * KNN_K + k];
                float dz = sDz[p * KNN_K + k];
                int gg = k & 7, hrow = k >> 3;
                float p0 = fmaf(dx, M0.x, fmaf(dy, M1.x, fmaf(dz, M2.x, b4.x)));
                float p1 = fmaf(dx, M0.y, fmaf(dy, M1.y, fmaf(dz, M2.y, b4.y)));
                float p2 = fmaf(dx, M0.z, fmaf(dy, M1.z, fmaf(dz, M2.z, b4.z)));
                float p3 = fmaf(dx, M0.w, fmaf(dy, M1.w, fmaf(dz, M2.w, b4.w)));
                apb[(((gg * 4 + 0) ^ swz) << 2) + hrow] = f2tf32(gelu_fast(p0));
                apb[(((gg * 4 + 1) ^ swz) << 2) + hrow] = f2tf32(gelu_fast(p1));
                apb[(((gg * 4 + 2) ^ swz) << 2) + hrow] = f2tf32(gelu_fast(p2));
                apb[(((gg * 4 + 3) ^ swz) << 2) + hrow] = f2tf32(gelu_fast(p3));
            }
        }
        __syncthreads();   // #3: Apack visible

        // ---- main MMA: 64x32 tile per warp over K=128 ----
        float acc[4][4][4];
#pragma unroll
        for (int mt = 0; mt < 4; mt++)
#pragma unroll
            for (int nt = 0; nt < 4; nt++)
#pragma unroll
                for (int q = 0; q < 4; q++) acc[mt][nt][q] = 0.f;

#pragma unroll 4
        for (int kk = 0; kk < 16; kk++) {
            const int ls = lane ^ (kk & 7);
            uint4 Af[4];
            uint2 Bf[4];
#pragma unroll
            for (int mt = 0; mt < 4; mt++)
                Af[mt] = sAp4[((mhalf * 4 + mt) * 16 + kk) * 32 + ls];
#pragma unroll
            for (int nt = 0; nt < 4; nt++)
                Bf[nt] = sBp2[((nquad * 4 + nt) * 16 + kk) * 32 + lane];
#pragma unroll
            for (int mt = 0; mt < 4; mt++)
#pragma unroll
                for (int nt = 0; nt < 4; nt++)
                    mma8(acc[mt][nt], Af[mt], Bf[nt]);
        }

        // ---- epilogue: + gather, max over k, store ----
#pragma unroll
        for (int mt = 0; mt < 4; mt++) {
            const int pp = mhalf * 4 + mt;
            const int ip = g * GRP + pp;
            const int j0 = sJn[pp * KNN_K + fg];
            const int j1 = sJn[pp * KNN_K + 8 + fg];
#pragma unroll
            for (int nt = 0; nt < 4; nt++) {
                const int c = 8 * (nquad * 4 + nt) + 2 * ftg;
                float2 ga = *(const float2*)(g_xp + (size_t)j0 * C + c);
                float2 gb = *(const float2*)(g_xp + (size_t)j1 * C + c);
                float v0 = fmaxf(acc[mt][nt][0] + ga.x, acc[mt][nt][2] + gb.x);
                float v1 = fmaxf(acc[mt][nt][1] + ga.y, acc[mt][nt][3] + gb.y);
#pragma unroll
                for (int s = 4; s <= 16; s <<= 1) {
                    v0 = fmaxf(v0, __shfl_xor_sync(0xffffffffu, v0, s));
                    v1 = fmaxf(v1, __shfl_xor_sync(0xffffffffu, v1, s));
                }
                if (fg == 0 && ip < N) {
                    float2 xc = *(const float2*)(g_xp + (size_t)ip * C + c);
                    float2 o;
                    o.x = v0 + sB3b[c] - xc.x;
                    o.y = v1 + sB3b[c + 1] - xc.y;
                    *(float2*)(g_xsmax + (size_t)ip * C + c) = o;
                }
            }
        }
        __syncthreads();   // #4: protect smem for next group
    }
}

// ---------------- kernel 3: BatchNorm ----------------
__global__ void bn_partial_kernel(int N) {
    int c = threadIdx.x;
    int rpb = (N + PB - 1) / PB;
    int r0 = blockIdx.x * rpb;
    int r1 = min(N, r0 + rpb);
    float s = 0.f, q = 0.f;
    for (int r = r0; r < r1; r++) {
        float v = g_xsmax[(size_t)r * C + c];
        s += v;
        q = fmaf(v, v, q);
    }
    g_part[blockIdx.x * C + c] = s;
    g_partsq[blockIdx.x * C + c] = q;
}

__global__ void bn_final_kernel(const float* __restrict__ gamma, const float* __restrict__ beta, int N) {
    int c = threadIdx.x;
    float s = 0.f, q = 0.f;
    for (int b = 0; b < PB; b++) { s += g_part[b * C + c]; q += g_partsq[b * C + c]; }
    float mean = s / (float)N;
    float var = q / (float)N - mean * mean;
    if (var < 0.f) var = 0.f;
    float sc = rsqrtf(var + EPS) * gamma[c];
    g_scale[c] = sc;
    g_shift[c] = beta[c] - mean * sc;
}

__global__ void bn_apply_kernel(float* __restrict__ out, int N) {
    int idx = blockIdx.x * blockDim.x + threadIdx.x;
    int total4 = N * (C / 4);
    if (idx >= total4) return;
    float4 v = ((const float4*)g_xsmax)[idx];
    int c4 = idx & 31;
    float4 sc = ((const float4*)g_scale)[c4];
    float4 sf = ((const float4*)g_shift)[c4];
    float4 o;
    o.x = fmaf(v.x, sc.x, sf.x);
    o.y = fmaf(v.y, sc.y, sf.y);
    o.z = fmaf(v.z, sc.z, sf.z);
    o.w = fmaf(v.w, sc.w, sf.w);
    ((float4*)out)[idx] = o;
}

// ---------------- launch ----------------
extern "C" void kernel_launch(void* const* d_in, const int* in_sizes, int n_in,
                              void* d_out, int out_size) {
    const float* xyz  = (const float*)d_in[0];
    const float* x    = (const float*)d_in[1];
    const int*   knn  = (const int*)d_in[2];
    const float* W    = (const float*)d_in[3];
    const float* m1w  = (const float*)d_in[4];
    const float* m1b  = (const float*)d_in[5];
    const float* m2w  = (const float*)d_in[6];
    const float* m2b  = (const float*)d_in[7];
    const float* m3aw = (const float*)d_in[8];
    const float* m3ab = (const float*)d_in[9];
    const float* m3bw = (const float*)d_in[10];
    const float* m3bb = (const float*)d_in[11];
    const float* gamma = (const float*)d_in[12];
    const float* beta  = (const float*)d_in[13];

    int N = in_sizes[0] / 3;

    static int sms = 0;
    if (sms == 0) {
        cudaDeviceGetAttribute(&sms, cudaDevAttrMultiProcessorCount, 0);
        cudaFuncSetAttribute(main_kernel, cudaFuncAttributeMaxDynamicSharedMemorySize, SMEM_BYTES);
    }

    fold_kernel<<<1, 256>>>(m1w, m1b, m2w, m2b, m3aw, m3ab);
    proj_kernel<<<(N + 31) / 32, 256>>>(x, W, N);
    main_kernel<<<sms, NTHR, SMEM_BYTES>>>(xyz, knn, m1w, m1b, m3bw, m3bb, N);
    bn_partial_kernel<<<PB, C>>>(N);
    bn_final_kernel<<<1, C>>>(gamma, beta, N);
    int total4 = N * (C / 4);
    bn_apply_kernel<<<(total4 + 255) / 256, 256>>>((float*)d_out, N);
}